// round 11
// baseline (speedup 1.0000x reference)
#include <cuda_runtime.h>
#include <cuda_fp16.h>
#include <cstdint>
#include <cstddef>
#include <mma.h>

using namespace nvcuda;

#define N_NODES    100000
#define N_TYPES    7
#define E_PER_TYPE 250000
#define DIM        128
#define N_PAD      100096          // 782 tiles * 128
#define NGB        (N_PAD / 128)   // 782 gemm blocks per type
#define SBLK       (E_PER_TYPE * 16 / 256)   // 15625 scatter blocks per type

#define LDA 36                     // A-stage row stride (floats)
#define LDB 132                    // W-stage row stride
#define LDS 132                    // epilogue staging row stride

// Scratch
__device__ __half g_yh[(size_t)N_TYPES * N_PAD * DIM];   // y fp16 (179 MB)
__device__ float  g_xt[(size_t)N_PAD * DIM];             // tf32-rounded x (padded)
__device__ float  g_Wt[N_TYPES * DIM * DIM];             // tf32-rounded W
__device__ float  g_cnt[N_TYPES * N_NODES];
__device__ float  g_inv[N_TYPES * N_NODES];

// ---------------------------------------------------------------------------
// helpers
// ---------------------------------------------------------------------------
__device__ __forceinline__ void cp_async16(unsigned int dst_smem, const void* src) {
    asm volatile("cp.async.cg.shared.global [%0], [%1], 16;"
                 :: "r"(dst_smem), "l"(src));
}
__device__ __forceinline__ void cp_commit() {
    asm volatile("cp.async.commit_group;");
}
template <int N>
__device__ __forceinline__ void cp_wait() {
    asm volatile("cp.async.wait_group %0;" :: "n"(N));
}
__device__ __forceinline__ unsigned int pack_h2(float a, float b) {
    __half2 h = __floats2half2_rn(a, b);
    return *reinterpret_cast<unsigned int*>(&h);
}

// ---------------------------------------------------------------------------
// Kernel 0: pre-round x (zero-padded) and W to tf32; zero g_cnt.
// ---------------------------------------------------------------------------
__global__ void cvt_kernel(const float4* __restrict__ x4,
                           const float4* __restrict__ W4) {
    const int NX = N_PAD * (DIM / 4);
    const int NW = N_TYPES * DIM * (DIM / 4);
    int idx = blockIdx.x * blockDim.x + threadIdx.x;
    if (idx < NX) {
        int row = idx >> 5;
        float4 v = make_float4(0.f, 0.f, 0.f, 0.f);
        if (row < N_NODES) {
            v = __ldg(&x4[idx]);
            v.x = wmma::__float_to_tf32(v.x);
            v.y = wmma::__float_to_tf32(v.y);
            v.z = wmma::__float_to_tf32(v.z);
            v.w = wmma::__float_to_tf32(v.w);
        }
        ((float4*)g_xt)[idx] = v;
    } else if (idx < NX + NW) {
        int wi = idx - NX;
        float4 v = __ldg(&W4[wi]);
        v.x = wmma::__float_to_tf32(v.x);
        v.y = wmma::__float_to_tf32(v.y);
        v.z = wmma::__float_to_tf32(v.z);
        v.w = wmma::__float_to_tf32(v.w);
        ((float4*)g_Wt)[wi] = v;
    }
    if (idx < N_TYPES * N_NODES) g_cnt[idx] = 0.f;   // replay-safe zero
}

// ---------------------------------------------------------------------------
// Kernel 1: in-degree per (type, dst). int4-vectorized edge reads.
// ---------------------------------------------------------------------------
__global__ void cnt_kernel(const int* __restrict__ ei) {
    int idx = blockIdx.x * blockDim.x + threadIdx.x;
    const int E4 = E_PER_TYPE / 4;              // 62500
    if (idx >= N_TYPES * E4) return;
    int t  = idx / E4;
    int e4 = idx - t * E4;
    const int4* dst4 = (const int4*)(ei + (size_t)t * 2 * E_PER_TYPE + E_PER_TYPE);
    int4 d = __ldg(&dst4[e4]);
    float* cb = g_cnt + t * N_NODES;
    if ((unsigned)d.x < (unsigned)N_NODES) atomicAdd(&cb[d.x], 1.0f);
    if ((unsigned)d.y < (unsigned)N_NODES) atomicAdd(&cb[d.y], 1.0f);
    if ((unsigned)d.z < (unsigned)N_NODES) atomicAdd(&cb[d.z], 1.0f);
    if ((unsigned)d.w < (unsigned)N_NODES) atomicAdd(&cb[d.w], 1.0f);
}

// ---------------------------------------------------------------------------
// Kernel 2: g_inv = 1 / (T * max(cnt,1))
// ---------------------------------------------------------------------------
__global__ void inv_kernel() {
    int i = blockIdx.x * blockDim.x + threadIdx.x;
    if (i < N_TYPES * N_NODES)
        g_inv[i] = 1.0f / ((float)N_TYPES * fmaxf(g_cnt[i], 1.0f));
}

// ---------------------------------------------------------------------------
// Kernel 3: out[n,:] = (1/T) * sum_t (cnt[t,n]>0) * b[t,:]
// ---------------------------------------------------------------------------
__global__ __launch_bounds__(256)
void init_out_kernel(const float* __restrict__ bg, float4* __restrict__ out4) {
    __shared__ float4 bs[N_TYPES * 32];
    int tid = threadIdx.x;
    if (tid < N_TYPES * 32) bs[tid] = __ldg(((const float4*)bg) + tid);
    __syncthreads();
    int idx = blockIdx.x * blockDim.x + tid;
    if (idx >= N_NODES * (DIM / 4)) return;
    int n = idx >> 5;
    int q = idx & 31;

    float c[N_TYPES];
#pragma unroll
    for (int t = 0; t < N_TYPES; t++) c[t] = g_cnt[t * N_NODES + n];

    float4 acc = make_float4(0.f, 0.f, 0.f, 0.f);
#pragma unroll
    for (int t = 0; t < N_TYPES; t++) {
        float f = (c[t] > 0.f) ? (1.0f / (float)N_TYPES) : 0.f;
        float4 bb = bs[t * 32 + q];
        acc.x = fmaf(f, bb.x, acc.x);
        acc.y = fmaf(f, bb.y, acc.y);
        acc.z = fmaf(f, bb.z, acc.z);
        acc.w = fmaf(f, bb.w, acc.w);
    }
    out4[(size_t)n * (DIM / 4) + q] = acc;
}

// ---------------------------------------------------------------------------
// GEMM block body: 128-row tile of y[t] = x @ W[t], tf32 wmma, fp16 store.
// BK=32 cp.async double-buffer (verbatim from the passing R8 kernel).
// ---------------------------------------------------------------------------
__device__ __forceinline__ void gemm_block(int t, int row0) {
    extern __shared__ float sm[];
    float* Ab[2] = {sm, sm + 128 * LDA};
    float* Wb[2] = {sm + 2 * 128 * LDA, sm + 2 * 128 * LDA + 32 * LDB};

    const int tid  = threadIdx.x;
    const int warp = tid >> 5;
    const int wr   = warp >> 2;              // 0..1
    const int wc   = warp & 3;               // 0..3

    unsigned int sAb[2] = {(unsigned int)__cvta_generic_to_shared(Ab[0]),
                           (unsigned int)__cvta_generic_to_shared(Ab[1])};
    unsigned int sWb[2] = {(unsigned int)__cvta_generic_to_shared(Wb[0]),
                           (unsigned int)__cvta_generic_to_shared(Wb[1])};

    const float* Asrc = g_xt + (size_t)row0 * DIM;
    const float* Wsrc = g_Wt + (size_t)t * DIM * DIM;

    auto load_stage = [&](int k0, int buf) {
#pragma unroll
        for (int i = 0; i < 4; i++) {
            int li = tid + i * 256;
            int r  = li >> 3;
            int c4 = li & 7;
            cp_async16(sAb[buf] + (unsigned int)(r * LDA + c4 * 4) * 4,
                       Asrc + (size_t)r * DIM + k0 + c4 * 4);
        }
#pragma unroll
        for (int i = 0; i < 4; i++) {
            int li = tid + i * 256;
            int r  = li >> 5;
            int c4 = li & 31;
            cp_async16(sWb[buf] + (unsigned int)(r * LDB + c4 * 4) * 4,
                       Wsrc + (size_t)(k0 + r) * DIM + c4 * 4);
        }
        cp_commit();
    };

    wmma::fragment<wmma::accumulator, 16, 16, 8, float> acc[4][2];
#pragma unroll
    for (int m = 0; m < 4; m++)
#pragma unroll
        for (int n = 0; n < 2; n++) wmma::fill_fragment(acc[m][n], 0.0f);

    load_stage(0, 0);

#pragma unroll
    for (int ks = 0; ks < 4; ks++) {
        cp_wait<0>();
        __syncthreads();
        if (ks < 3) load_stage((ks + 1) * 32, (ks + 1) & 1);

        float* Ac = Ab[ks & 1];
        float* Wc = Wb[ks & 1];
#pragma unroll
        for (int sk = 0; sk < 4; sk++) {
            wmma::fragment<wmma::matrix_a, 16, 16, 8, wmma::precision::tf32,
                           wmma::row_major> af[4];
            wmma::fragment<wmma::matrix_b, 16, 16, 8, wmma::precision::tf32,
                           wmma::row_major> bf[2];
#pragma unroll
            for (int m = 0; m < 4; m++)
                wmma::load_matrix_sync(af[m],
                    Ac + (wr * 64 + m * 16) * LDA + sk * 8, LDA);
#pragma unroll
            for (int n = 0; n < 2; n++)
                wmma::load_matrix_sync(bf[n],
                    Wc + (sk * 8) * LDB + wc * 32 + n * 16, LDB);
#pragma unroll
            for (int m = 0; m < 4; m++)
#pragma unroll
                for (int n = 0; n < 2; n++)
                    wmma::mma_sync(acc[m][n], af[m], bf[n], acc[m][n]);
        }
    }

    __syncthreads();
    float* stg = sm;                         // [128][LDS]
#pragma unroll
    for (int m = 0; m < 4; m++)
#pragma unroll
        for (int n = 0; n < 2; n++)
            wmma::store_matrix_sync(
                stg + (wr * 64 + m * 16) * LDS + wc * 32 + n * 16,
                acc[m][n], LDS, wmma::mem_row_major);
    __syncthreads();

    __half* ybase = g_yh + ((size_t)t * N_PAD + row0) * DIM;
#pragma unroll
    for (int i = 0; i < 8; i++) {
        int li = tid + i * 256;
        int r  = li >> 4;
        int g  = li & 15;
        float4 v0 = *(float4*)&stg[r * LDS + g * 8];
        float4 v1 = *(float4*)&stg[r * LDS + g * 8 + 4];
        uint4 u;
        u.x = pack_h2(v0.x, v0.y);
        u.y = pack_h2(v0.z, v0.w);
        u.z = pack_h2(v1.x, v1.y);
        u.w = pack_h2(v1.z, v1.w);
        *(uint4*)(ybase + (size_t)r * DIM + g * 8) = u;
    }
}

// ---------------------------------------------------------------------------
// Scatter block body: 16 edges per block, 16 lanes per edge; uint4 fp16 gather
// + 2x red.global.add.v4.f32 into L2-resident out (verbatim R8 math).
// ---------------------------------------------------------------------------
__device__ __forceinline__ void scatter_block(const int* __restrict__ ei,
                                              float* __restrict__ out,
                                              int t, int sbid) {
    int gt = sbid * 256 + threadIdx.x;
    int edge = gt >> 4;                      // 16 lanes per edge
    int sub = threadIdx.x & 15;
    if (edge >= E_PER_TYPE) return;

    const int* base = ei + (size_t)t * 2 * E_PER_TYPE;
    int src = __ldg(&base[edge]);
    int dst = __ldg(&base[E_PER_TYPE + edge]);
    if ((unsigned)src >= (unsigned)N_NODES ||
        (unsigned)dst >= (unsigned)N_NODES) return;

    float s = __ldg(&g_inv[t * N_NODES + dst]);
    const uint4* yrow = (const uint4*)(g_yh + ((size_t)t * N_PAD + src) * DIM);
    uint4 p = __ldg(&yrow[sub]);             // 16 B = 8 halfs

    __half2 h0 = *reinterpret_cast<__half2*>(&p.x);
    __half2 h1 = *reinterpret_cast<__half2*>(&p.y);
    __half2 h2 = *reinterpret_cast<__half2*>(&p.z);
    __half2 h3 = *reinterpret_cast<__half2*>(&p.w);
    float2 f0 = __half22float2(h0);
    float2 f1 = __half22float2(h1);
    float2 f2 = __half22float2(h2);
    float2 f3 = __half22float2(h3);

    float* q = out + (size_t)dst * DIM + sub * 8;
    asm volatile("red.global.add.v4.f32 [%0], {%1, %2, %3, %4};"
                 :: "l"(q), "f"(f0.x * s), "f"(f0.y * s),
                    "f"(f1.x * s), "f"(f1.y * s) : "memory");
    asm volatile("red.global.add.v4.f32 [%0], {%1, %2, %3, %4};"
                 :: "l"(q + 4), "f"(f2.x * s), "f"(f2.y * s),
                    "f"(f3.x * s), "f"(f3.y * s) : "memory");
}

// ---------------------------------------------------------------------------
// Fused step: gemm blocks for type tg (if tg>=0) + scatter blocks for type ts
// (if ts>=0) in ONE launch. gemm blocks lead the grid so tensor work starts
// immediately; scatter blocks backfill SM capacity alongside. The launch
// boundary between steps orders gemm_t before scatter_t.
// ---------------------------------------------------------------------------
__global__ __launch_bounds__(256)
void fused_kernel(const int* __restrict__ ei, float* __restrict__ out,
                  int tg, int ts) {
    int ngb = (tg >= 0) ? NGB : 0;
    if ((int)blockIdx.x < ngb) {
        gemm_block(tg, blockIdx.x * 128);
    } else if (ts >= 0) {
        scatter_block(ei, out, ts, blockIdx.x - ngb);
    }
}

// ---------------------------------------------------------------------------
// Inputs: x [100000,128] f32, edge_index [7,2,250000] int32,
//         W [7,128,128] f32, b [7,128] f32.  Output: [100000,128] f32.
// All launches on the legacy stream (the only capture-safe pattern).
// ---------------------------------------------------------------------------
extern "C" void kernel_launch(void* const* d_in, const int* in_sizes, int n_in,
                              void* d_out, int out_size) {
    (void)in_sizes; (void)n_in; (void)out_size;
    const float* x   = (const float*)d_in[0];
    const int*   ei  = (const int*)d_in[1];
    const float* W   = (const float*)d_in[2];
    const float* b   = (const float*)d_in[3];
    float*       out = (float*)d_out;

    const int smem_bytes = (2 * 128 * LDA + 2 * 32 * LDB) * 4;   // 70656
    cudaFuncSetAttribute(fused_kernel,
                         cudaFuncAttributeMaxDynamicSharedMemorySize,
                         smem_bytes);

    int ncvt = N_PAD * (DIM / 4) + N_TYPES * DIM * (DIM / 4);
    cvt_kernel<<<(ncvt + 255) / 256, 256>>>((const float4*)x,
                                            (const float4*)W);

    cnt_kernel<<<(N_TYPES * (E_PER_TYPE / 4) + 255) / 256, 256>>>(ei);

    inv_kernel<<<(N_TYPES * N_NODES + 255) / 256, 256>>>();

    int ninit = N_NODES * (DIM / 4);
    init_out_kernel<<<(ninit + 255) / 256, 256>>>(b, (float4*)out);

    // 8 fused steps: [g0], [g1+s0], ..., [g6+s5], [s6]
    for (int step = 0; step <= N_TYPES; step++) {
        int tg = (step < N_TYPES) ? step : -1;
        int ts = step - 1;                   // -1 on first step
        int grid = ((tg >= 0) ? NGB : 0) + ((ts >= 0) ? SBLK : 0);
        fused_kernel<<<grid, 256, smem_bytes>>>(ei, out, tg, ts);
    }
}